// round 4
// baseline (speedup 1.0000x reference)
#include <cuda_runtime.h>
#include <math.h>

#define Tt   64
#define Bb   128
#define Ee   1024
#define Hh   1024
#define Vv   10000
#define NBLK 12
#define GRID_R 128
#define VPAD 10112
#define PIPE 3

// ---------------- scratch (device globals; no allocation allowed) ----------------
__device__ __align__(16) float g_XC[Tt*Bb*Hh];
__device__ __align__(16) float g_XH[Tt*Bb*Hh];
__device__ __align__(16) float g_OUT[Tt*Bb*Hh];    // tf32-rounded pre-clip hidden
__device__ __align__(16) float g_H[Bb*Hh];         // carried hidden f32
__device__ __align__(16) float g_Htf[Bb*Hh];       // tf32-rounded twin
__device__ __align__(16) float g_Pc[4*Bb*Hh];
__device__ __align__(16) float g_Ph[4*Bb*Hh];
__device__ __align__(16) float g_Wc[NBLK*Hh*Hh];
__device__ __align__(16) float g_Wh[NBLK*Hh*Hh];
__device__ __align__(16) float g_We[Vv*Ee];
__device__ __align__(16) float g_Wx[2*Hh*Ee];
__device__ __align__(16) float g_Wd[VPAD*Hh];
__device__ unsigned g_arr[GRID_R];
__device__ unsigned g_rel;

// ---------------- helpers ----------------
__device__ __forceinline__ unsigned f2tf32(float x){
  unsigned u; asm("cvt.rna.tf32.f32 %0, %1;" : "=r"(u) : "f"(x)); return u;
}
__device__ __forceinline__ float rndtf(float x){ return __uint_as_float(f2tf32(x)); }

__device__ __forceinline__ void mma_tf32(float* c, const unsigned* a, const unsigned* b){
  asm volatile(
    "mma.sync.aligned.m16n8k8.row.col.f32.tf32.tf32.f32 "
    "{%0,%1,%2,%3}, {%4,%5,%6,%7}, {%8,%9}, {%0,%1,%2,%3};\n"
    : "+f"(c[0]), "+f"(c[1]), "+f"(c[2]), "+f"(c[3])
    : "r"(a[0]), "r"(a[1]), "r"(a[2]), "r"(a[3]), "r"(b[0]), "r"(b[1]));
}

__device__ __forceinline__ void cpa16(void* smemp, const void* gmem){
  unsigned s = (unsigned)__cvta_generic_to_shared(smemp);
  asm volatile("cp.async.cg.shared.global [%0], [%1], 16;\n" :: "r"(s), "l"(gmem));
}
__device__ __forceinline__ void cpa_commit(){ asm volatile("cp.async.commit_group;\n"); }
template<int N> __device__ __forceinline__ void cpa_wait(){
  asm volatile("cp.async.wait_group %0;\n" :: "n"(N));
}

__device__ __forceinline__ float sigm(float x){ return 1.f/(1.f + expf(-x)); }

// grid barrier: per-CTA flag words, CTA0 scans, single release word.
__device__ __forceinline__ void gsync(unsigned &ep){
  ep++;
  __syncthreads();
  if (blockIdx.x == 0){
    if (threadIdx.x > 0 && threadIdx.x < GRID_R){
      while (*(volatile unsigned*)&g_arr[threadIdx.x] < ep) { }
    }
    __syncthreads();
    if (threadIdx.x == 0){ __threadfence(); *(volatile unsigned*)&g_rel = ep; }
  } else {
    if (threadIdx.x == 0){
      __threadfence();
      *(volatile unsigned*)&g_arr[blockIdx.x] = ep;
      while (*(volatile unsigned*)&g_rel < ep) { }
    }
  }
  __syncthreads();
  __threadfence();
}

// warp tile 64x32 (mi4 x ni4), k-block 32, smem row stride 36
__device__ __forceinline__ void compute_64x32(const float* Af, const float* Bf,
      float acc[4][4][4], int wm, int wn, int g, int tg){
  const unsigned* As = (const unsigned*)Af;
  const unsigned* Bs = (const unsigned*)Bf;
#pragma unroll
  for (int ks = 0; ks < 32; ks += 8){
    unsigned a[4][4], b[4][2];
#pragma unroll
    for (int mi = 0; mi < 4; mi++){
      int r = wm + mi*16 + g;
      a[mi][0] = As[r*36 + ks+tg];
      a[mi][1] = As[(r+8)*36 + ks+tg];
      a[mi][2] = As[r*36 + ks+tg+4];
      a[mi][3] = As[(r+8)*36 + ks+tg+4];
    }
#pragma unroll
    for (int ni = 0; ni < 4; ni++){
      int rr = wn + ni*8 + g;
      b[ni][0] = Bs[rr*36 + ks+tg];
      b[ni][1] = Bs[rr*36 + ks+tg+4];
    }
#pragma unroll
    for (int mi = 0; mi < 4; mi++)
#pragma unroll
      for (int ni = 0; ni < 4; ni++)
        mma_tf32(acc[mi][ni], a[mi], b[ni]);
  }
}

// warp tile 64x16 (mi4 x ni2) for the recurrence
__device__ __forceinline__ void compute_64x16(const float* Af, const float* Bf,
      float acc[4][2][4], int wm, int wn, int g, int tg){
  const unsigned* As = (const unsigned*)Af;
  const unsigned* Bs = (const unsigned*)Bf;
#pragma unroll
  for (int ks = 0; ks < 32; ks += 8){
    unsigned a[4][4], b[2][2];
#pragma unroll
    for (int mi = 0; mi < 4; mi++){
      int r = wm + mi*16 + g;
      a[mi][0] = As[r*36 + ks+tg];
      a[mi][1] = As[(r+8)*36 + ks+tg];
      a[mi][2] = As[r*36 + ks+tg+4];
      a[mi][3] = As[(r+8)*36 + ks+tg+4];
    }
#pragma unroll
    for (int ni = 0; ni < 2; ni++){
      int rr = wn + ni*8 + g;
      b[ni][0] = Bs[rr*36 + ks+tg];
      b[ni][1] = Bs[rr*36 + ks+tg+4];
    }
#pragma unroll
    for (int mi = 0; mi < 4; mi++)
#pragma unroll
      for (int ni = 0; ni < 2; ni++)
        mma_tf32(acc[mi][ni], a[mi], b[ni]);
  }
}

// ---------------- prep: single kernel, tf32-round all operands ----------------
#define S_WC  3145728L
#define S_WH  3145728L
#define S_WE  2560000L
#define S_WX   524288L
#define S_WD  2588672L
__global__ void __launch_bounds__(256) prep_all(
    const float* __restrict__ w_hc, const float* __restrict__ edge_c,
    const float* __restrict__ w_hh, const float* __restrict__ edge_h,
    const float* __restrict__ embW, const float* __restrict__ wxcW,
    const float* __restrict__ wxhW, const float* __restrict__ decW)
{
  long i = (long)blockIdx.x*256 + threadIdx.x;
  const long F4 = (long)Hh*Hh/4;          // 262144
  float4 v; float4* dst;
  if (i < S_WC){
    v = (i < F4) ? ((const float4*)w_hc)[i] : ((const float4*)edge_c)[i-F4];
    dst = ((float4*)g_Wc) + i;
  } else if ((i -= S_WC) < S_WH){
    v = (i < F4) ? ((const float4*)w_hh)[i] : ((const float4*)edge_h)[i-F4];
    dst = ((float4*)g_Wh) + i;
  } else if ((i -= S_WH) < S_WE){
    v = ((const float4*)embW)[i];
    dst = ((float4*)g_We) + i;
  } else if ((i -= S_WE) < S_WX){
    const long G4 = (long)Hh*Ee/4;
    v = (i < G4) ? ((const float4*)wxcW)[i] : ((const float4*)wxhW)[i-G4];
    dst = ((float4*)g_Wx) + i;
  } else if ((i -= S_WX) < S_WD){
    long row = (i*4) >> 10;
    v = (row < Vv) ? ((const float4*)decW)[i] : make_float4(0.f,0.f,0.f,0.f);
    dst = ((float4*)g_Wd) + i;
  } else return;
  float4 r; r.x=rndtf(v.x); r.y=rndtf(v.y); r.z=rndtf(v.z); r.w=rndtf(v.w);
  *dst = r;
}

// ---------------- phase 1: input projections ----------------
__global__ void __launch_bounds__(256) xproj_kernel(
    const int* __restrict__ tokens,
    const float* __restrict__ wxcB, const float* __restrict__ wxhB)
{
  extern __shared__ float sm[];
  float* Ab = sm;
  float* Bbf = sm + PIPE*128*36;
  __shared__ int toks[128];
  const int tid = threadIdx.x;
  const int n0 = blockIdx.x * 128;
  const int m0 = blockIdx.y * 128;
  const int mat = blockIdx.z;
  const float* W    = g_Wx + (size_t)mat*Hh*Ee;
  const float* bias = mat ? wxhB : wxcB;
  float* Cout = mat ? g_XH : g_XC;
  if (tid < 128) toks[tid] = tokens[m0 + tid];
  __syncthreads();
  const int lane = tid & 31, warp = tid >> 5;
  const int wm = (warp & 1) * 64, wn = (warp >> 1) * 32;
  const int g = lane >> 2, tg = lane & 3;

  float acc[4][4][4];
#pragma unroll
  for (int a=0;a<4;a++)
#pragma unroll
    for (int b=0;b<4;b++)
#pragma unroll
      for (int c=0;c<4;c++) acc[a][b][c]=0.f;

  auto load_tile = [&](int p, int kbi){
    int kb = kbi * 32;
#pragma unroll
    for (int i = 0; i < 4; i++){
      int idx = tid + i*256, row = idx>>3, c4 = (idx&7)*4;
      cpa16(&Ab[p*4608 + row*36 + c4], g_We + (size_t)toks[row]*Ee + kb + c4);
      cpa16(&Bbf[p*4608 + row*36 + c4], W + (size_t)(n0+row)*Ee + kb + c4);
    }
  };

#pragma unroll
  for (int p = 0; p < PIPE-1; p++){ load_tile(p, p); cpa_commit(); }
  for (int it = 0; it < 32; it++){
    cpa_wait<PIPE-2>();
    __syncthreads();
    int nx = it + PIPE - 1;
    if (nx < 32) load_tile(nx % PIPE, nx);
    cpa_commit();
    compute_64x32(Ab + (it%PIPE)*4608, Bbf + (it%PIPE)*4608, acc, wm, wn, g, tg);
  }

#pragma unroll
  for (int mi=0; mi<4; mi++){
    int r = m0 + wm + mi*16 + g;
#pragma unroll
    for (int ni=0; ni<4; ni++){
      int c = n0 + wn + ni*8 + 2*tg;
      float b0 = bias[c], b1 = bias[c+1];
      size_t o = (size_t)r*Hh + c;
      Cout[o]        = acc[mi][ni][0] + b0;
      Cout[o+1]      = acc[mi][ni][1] + b1;
      Cout[o+8*Hh]   = acc[mi][ni][2] + b0;
      Cout[o+8*Hh+1] = acc[mi][ni][3] + b1;
    }
  }
}

// ---------------- phase 2: persistent recurrence ----------------
// 128 CTAs: kc(4) x nt(16) x mat(2). CTA tile 128(M) x 64(N) x 256(K).
// Weights for stage s+1 prefetched during stage s epilogue. A triple-buffered.
__global__ void __launch_bounds__(256) rnn_kernel(float* __restrict__ outp)
{
  extern __shared__ float sm[];
  float* Aw = sm;              // 3 * 128*36 floats
  float* Bw = sm + 3*4608;     // 8 * 64*36 floats (full stage of weight tiles)
  __shared__ float red[9];
  const int tid = threadIdx.x;
  const int bid = blockIdx.x;
  const int lane = tid & 31, warp = tid >> 5;
  const int wm = (warp & 1) * 64, wn = (warp >> 1) * 16;
  const int g = lane >> 2, tg = lane & 3;
  const int kc  = bid & 3;
  const int nt  = (bid >> 2) & 15;
  const int mat = bid >> 6;
  const int n0 = nt * 64;
  const int k0 = kc * 256;
  const int f  = bid * 256 + tid;      // float4 index over 128x1024
  unsigned ep = 0;

  const float* Wbase = mat ? g_Wh : g_Wc;

  auto load_B = [&](int s){
    const float* W = Wbase + (size_t)s*Hh*Hh;
#pragma unroll
    for (int i = 0; i < 16; i++){
      int idx = tid + i*256;
      int kb = idx >> 9;
      int j  = idx & 511;
      int row = j >> 3, c4 = (j & 7) * 4;
      cpa16(&Bw[kb*2304 + row*36 + c4], W + (size_t)(n0+row)*Hh + k0 + kb*32 + c4);
    }
  };
  auto load_A = [&](int p, int kbi){
    int kb = kbi * 32;
#pragma unroll
    for (int i = 0; i < 4; i++){
      int idx = tid + i*256, row = idx>>3, c4 = (idx&7)*4;
      cpa16(&Aw[p*4608 + row*36 + c4], g_Htf + (size_t)row*Hh + k0 + kb + c4);
    }
  };

  // prefetch stage-0 weights immediately (independent of h)
  load_B(0); cpa_commit();

  // h0 = 0
  {
    float4 z = make_float4(0.f,0.f,0.f,0.f);
    ((float4*)g_H)[f]   = z;
    ((float4*)g_Htf)[f] = z;
  }
  gsync(ep);

  for (int t = 0; t < Tt; t++){
    for (int s = 0; s < NBLK; s++){
      float acc[4][2][4];
#pragma unroll
      for (int a=0;a<4;a++)
#pragma unroll
        for (int b2=0;b2<2;b2++)
#pragma unroll
          for (int c=0;c<4;c++) acc[a][b2][c]=0.f;

      load_A(0, 0); cpa_commit();
      load_A(1, 1); cpa_commit();
#pragma unroll 1
      for (int it = 0; it < 8; it++){
        cpa_wait<1>();
        __syncthreads();
        if (it + 2 < 8) load_A((it+2)%3, it+2);
        cpa_commit();
        compute_64x16(Aw + (it%3)*4608, Bw + it*2304, acc, wm, wn, g, tg);
      }

      // ALL warps must be done reading Bw before prefetching next weights
      __syncthreads();
      {
        int sn = s + 1; if (sn == NBLK) sn = 0;
        load_B(sn); cpa_commit();
      }

      // write split-K partial
      float* Pd = (mat ? g_Ph : g_Pc) + ((size_t)kc << 17);
#pragma unroll
      for (int mi=0; mi<4; mi++){
        int r = wm + mi*16 + g;
#pragma unroll
        for (int ni=0; ni<2; ni++){
          int c = n0 + wn + ni*8 + 2*tg;
          Pd[(size_t)r*Hh + c]       = acc[mi][ni][0];
          Pd[(size_t)r*Hh + c+1]     = acc[mi][ni][1];
          Pd[(size_t)(r+8)*Hh + c]   = acc[mi][ni][2];
          Pd[(size_t)(r+8)*Hh + c+1] = acc[mi][ni][3];
        }
      }
      gsync(ep);

      // fused reduce + gate + activation + blend; thread f owns 4 floats of row bid
      {
        float4 sc = make_float4(0.f,0.f,0.f,0.f);
        float4 sh = make_float4(0.f,0.f,0.f,0.f);
#pragma unroll
        for (int k = 0; k < 4; k++){
          float4 a  = ((const float4*)(g_Pc + ((size_t)k<<17)))[f];
          sc.x += a.x; sc.y += a.y; sc.z += a.z; sc.w += a.w;
          float4 b2 = ((const float4*)(g_Ph + ((size_t)k<<17)))[f];
          sh.x += b2.x; sh.y += b2.y; sh.z += b2.z; sh.w += b2.w;
        }
        if (s == 0){
          float4 a  = ((const float4*)g_XC)[((size_t)t<<15) + f];
          sc.x += a.x; sc.y += a.y; sc.z += a.z; sc.w += a.w;
          float4 b2 = ((const float4*)g_XH)[((size_t)t<<15) + f];
          sh.x += b2.x; sh.y += b2.y; sh.z += b2.z; sh.w += b2.w;
        }
        float4 h = ((const float4*)g_H)[f];
        const bool use_tanh = (s == 0) || (s & 1);
        float gx = sigm(sc.x), gy = sigm(sc.y), gz = sigm(sc.z), gw = sigm(sc.w);
        float ax = use_tanh ? tanhf(sh.x) : fmaxf(sh.x, 0.f);
        float ay = use_tanh ? tanhf(sh.y) : fmaxf(sh.y, 0.f);
        float az = use_tanh ? tanhf(sh.z) : fmaxf(sh.z, 0.f);
        float aw = use_tanh ? tanhf(sh.w) : fmaxf(sh.w, 0.f);
        float4 hn;
        hn.x = gx*ax + (1.f-gx)*h.x;
        hn.y = gy*ay + (1.f-gy)*h.y;
        hn.z = gz*az + (1.f-gz)*h.z;
        hn.w = gw*aw + (1.f-gw)*h.w;

        if (s == NBLK-1){
          // pre-clip output (decoder input), tf32-rounded
          float4 pre;
          pre.x=rndtf(hn.x); pre.y=rndtf(hn.y); pre.z=rndtf(hn.z); pre.w=rndtf(hn.w);
          ((float4*)g_OUT)[((size_t)t<<15) + f] = pre;
          // fused per-row norm clip: this CTA owns exactly row bid
          float ss = hn.x*hn.x + hn.y*hn.y + hn.z*hn.z + hn.w*hn.w;
#pragma unroll
          for (int off = 16; off > 0; off >>= 1) ss += __shfl_xor_sync(0xffffffffu, ss, off);
          if (lane == 0) red[warp] = ss;
          __syncthreads();
          if (tid == 0){
            float tot = 0.f;
#pragma unroll
            for (int w2 = 0; w2 < 8; w2++) tot += red[w2];
            float nrm = sqrtf(tot);
            red[8] = (nrm > 25.f) ? (25.f / nrm) : 1.f;
          }
          __syncthreads();
          float scl = red[8];
          hn.x *= scl; hn.y *= scl; hn.z *= scl; hn.w *= scl;
        }
        ((float4*)g_H)[f] = hn;
        float4 hr; hr.x=rndtf(hn.x); hr.y=rndtf(hn.y); hr.z=rndtf(hn.z); hr.w=rndtf(hn.w);
        ((float4*)g_Htf)[f] = hr;
      }
      gsync(ep);
    }
  }

  // hT (clipped final hidden) appended after decoded
  {
    float4 h = ((const float4*)g_H)[f];
    float* o = outp + (size_t)Tt*Bb*Vv + (size_t)f*4;
    o[0]=h.x; o[1]=h.y; o[2]=h.z; o[3]=h.w;
  }
}

// ---------------- phase 3: decoder GEMM ----------------
__global__ void __launch_bounds__(256) dec_kernel(
  const float* __restrict__ decB, float* __restrict__ outp)
{
  extern __shared__ float sm[];
  float* Ab = sm;
  float* Bbf = sm + PIPE*128*36;
  const int tid = threadIdx.x;
  const int n0 = blockIdx.x * 128;
  const int m0 = blockIdx.y * 128;
  const int lane = tid & 31, warp = tid >> 5;
  const int wm = (warp & 1) * 64, wn = (warp >> 1) * 32;
  const int g = lane >> 2, tg = lane & 3;
  float acc[4][4][4];
#pragma unroll
  for (int a=0;a<4;a++)
#pragma unroll
    for (int b=0;b<4;b++)
#pragma unroll
      for (int c=0;c<4;c++) acc[a][b][c]=0.f;

  auto load_tile = [&](int p, int kbi){
    int kb = kbi * 32;
#pragma unroll
    for (int i = 0; i < 4; i++){
      int idx = tid + i*256, row = idx>>3, c4 = (idx&7)*4;
      cpa16(&Ab[p*4608 + row*36 + c4], g_OUT + (size_t)(m0+row)*Hh + kb + c4);
      cpa16(&Bbf[p*4608 + row*36 + c4], g_Wd + (size_t)(n0+row)*Hh + kb + c4);
    }
  };

#pragma unroll
  for (int p = 0; p < PIPE-1; p++){ load_tile(p, p); cpa_commit(); }
  for (int it = 0; it < 32; it++){
    cpa_wait<PIPE-2>();
    __syncthreads();
    int nx = it + PIPE - 1;
    if (nx < 32) load_tile(nx % PIPE, nx);
    cpa_commit();
    compute_64x32(Ab + (it%PIPE)*4608, Bbf + (it%PIPE)*4608, acc, wm, wn, g, tg);
  }

#pragma unroll
  for (int mi=0;mi<4;mi++){
    int r = m0 + wm + mi*16 + g;
#pragma unroll
    for (int ni=0;ni<4;ni++){
      int c = n0 + wn + ni*8 + 2*tg;
      if (c < Vv){
        float b0 = decB[c], b1 = decB[c+1];
        size_t o  = (size_t)r*Vv + c;
        size_t o2 = o + (size_t)8*Vv;
        outp[o]    = acc[mi][ni][0] + b0;
        outp[o+1]  = acc[mi][ni][1] + b1;
        outp[o2]   = acc[mi][ni][2] + b0;
        outp[o2+1] = acc[mi][ni][3] + b1;
      }
    }
  }
}

// ---------------- launch ----------------
extern "C" void kernel_launch(void* const* d_in, const int* in_sizes, int n_in,
                              void* d_out, int out_size){
  const int*   tokens = (const int*)  d_in[0];
  const float* embW   = (const float*)d_in[1];
  const float* wxcW   = (const float*)d_in[2];
  const float* wxcB   = (const float*)d_in[3];
  const float* wxhW   = (const float*)d_in[4];
  const float* wxhB   = (const float*)d_in[5];
  const float* w_hc   = (const float*)d_in[6];
  const float* w_hh   = (const float*)d_in[7];
  const float* edge_h = (const float*)d_in[8];
  const float* edge_c = (const float*)d_in[9];
  const float* decW   = (const float*)d_in[10];
  const float* decB   = (const float*)d_in[11];
  float* outp = (float*)d_out;
  (void)in_sizes; (void)n_in; (void)out_size;

  const int RNN_SMEM  = (3*4608 + 8*2304) * 4;         // 129024
  const int GEMM_SMEM = PIPE * (128*36 + 128*36) * 4;  // 110592
  cudaFuncSetAttribute(xproj_kernel, cudaFuncAttributeMaxDynamicSharedMemorySize, GEMM_SMEM);
  cudaFuncSetAttribute(rnn_kernel,   cudaFuncAttributeMaxDynamicSharedMemorySize, RNN_SMEM);
  cudaFuncSetAttribute(dec_kernel,   cudaFuncAttributeMaxDynamicSharedMemorySize, GEMM_SMEM);

  // reset barrier flags (capturable memset nodes)
  void *pArr = nullptr, *pRel = nullptr;
  cudaGetSymbolAddress(&pArr, g_arr);
  cudaGetSymbolAddress(&pRel, g_rel);
  cudaMemsetAsync(pArr, 0, sizeof(unsigned)*GRID_R);
  cudaMemsetAsync(pRel, 0, sizeof(unsigned));

  const long PREP_TOTAL = S_WC + S_WH + S_WE + S_WX + S_WD;
  prep_all<<<(unsigned)((PREP_TOTAL + 255) / 256), 256>>>(
      w_hc, edge_c, w_hh, edge_h, embW, wxcW, wxhW, decW);

  xproj_kernel<<<dim3(8, 64, 2), 256, GEMM_SMEM>>>(tokens, wxcB, wxhB);
  rnn_kernel<<<GRID_R, 256, RNN_SMEM>>>(outp);
  dec_kernel<<<dim3(VPAD/128, 64), 256, GEMM_SMEM>>>(decB, outp);
}

// round 7
// speedup vs baseline: 1.2873x; 1.2873x over previous
#include <cuda_runtime.h>
#include <cuda_fp16.h>
#include <math.h>

#define Tt   64
#define Bb   128
#define Ee   1024
#define Hh   1024
#define Vv   10000
#define NBLK 12
#define GRID_R 128
#define VPAD 10112
#define PIPE 3

// ---------------- scratch (device globals) ----------------
__device__ __align__(16) float  g_XC[Tt*Bb*Hh];     // x @ wxc^T + b (f32, tf32 GEMM)
__device__ __align__(16) float  g_XH[Tt*Bb*Hh];
__device__ __align__(16) float  g_OUT[Tt*Bb*Hh];    // tf32-rounded pre-clip hidden (decoder A)
__device__ __align__(16) float  g_H[Bb*Hh];         // carried hidden f32
__device__ __align__(16) __half g_Hhp[Bb*Hh];       // fp16 twin (recurrence GEMM A)
__device__ __align__(16) float  g_Pc[4*Bb*Hh];
__device__ __align__(16) float  g_Ph[4*Bb*Hh];
__device__ __align__(16) __half g_Wc[NBLK*Hh*Hh];   // fp16 [w_hc, edge_c x11]
__device__ __align__(16) __half g_Wh[NBLK*Hh*Hh];   // fp16 [w_hh, edge_h x11]
__device__ __align__(16) float  g_We[Vv*Ee];        // tf32 embedding
__device__ __align__(16) float  g_Wx[2*Hh*Ee];      // tf32 wxc, wxh
__device__ __align__(16) float  g_Wd[VPAD*Hh];      // tf32 + zero-padded dec_W
__device__ unsigned g_arr[GRID_R];
__device__ unsigned g_rel;

// ---------------- helpers ----------------
__device__ __forceinline__ unsigned f2tf32(float x){
  unsigned u; asm("cvt.rna.tf32.f32 %0, %1;" : "=r"(u) : "f"(x)); return u;
}
__device__ __forceinline__ float rndtf(float x){ return __uint_as_float(f2tf32(x)); }

__device__ __forceinline__ uint2 pack4h(float4 v){
  __half2 a = __floats2half2_rn(v.x, v.y);
  __half2 b = __floats2half2_rn(v.z, v.w);
  uint2 u;
  u.x = *(unsigned*)&a;
  u.y = *(unsigned*)&b;
  return u;
}

__device__ __forceinline__ void mma_tf32(float* c, const unsigned* a, const unsigned* b){
  asm volatile(
    "mma.sync.aligned.m16n8k8.row.col.f32.tf32.tf32.f32 "
    "{%0,%1,%2,%3}, {%4,%5,%6,%7}, {%8,%9}, {%0,%1,%2,%3};\n"
    : "+f"(c[0]), "+f"(c[1]), "+f"(c[2]), "+f"(c[3])
    : "r"(a[0]), "r"(a[1]), "r"(a[2]), "r"(a[3]), "r"(b[0]), "r"(b[1]));
}

__device__ __forceinline__ void mma_fp16(float* c, const unsigned* a, const unsigned* b){
  asm volatile(
    "mma.sync.aligned.m16n8k16.row.col.f32.f16.f16.f32 "
    "{%0,%1,%2,%3}, {%4,%5,%6,%7}, {%8,%9}, {%0,%1,%2,%3};\n"
    : "+f"(c[0]), "+f"(c[1]), "+f"(c[2]), "+f"(c[3])
    : "r"(a[0]), "r"(a[1]), "r"(a[2]), "r"(a[3]), "r"(b[0]), "r"(b[1]));
}

__device__ __forceinline__ void cpa16(void* smemp, const void* gmem){
  unsigned s = (unsigned)__cvta_generic_to_shared(smemp);
  asm volatile("cp.async.cg.shared.global [%0], [%1], 16;\n" :: "r"(s), "l"(gmem));
}
__device__ __forceinline__ void cpa_commit(){ asm volatile("cp.async.commit_group;\n"); }
template<int N> __device__ __forceinline__ void cpa_wait(){
  asm volatile("cp.async.wait_group %0;\n" :: "n"(N));
}

__device__ __forceinline__ float sigm(float x){ return 1.f/(1.f + expf(-x)); }

// grid barrier: per-CTA flag words, CTA0 scans, single release word.
__device__ __forceinline__ void gsync(unsigned &ep){
  ep++;
  __syncthreads();
  if (blockIdx.x == 0){
    if (threadIdx.x > 0 && threadIdx.x < GRID_R){
      while (*(volatile unsigned*)&g_arr[threadIdx.x] < ep) { }
    }
    __syncthreads();
    if (threadIdx.x == 0){ __threadfence(); *(volatile unsigned*)&g_rel = ep; }
  } else {
    if (threadIdx.x == 0){
      __threadfence();
      *(volatile unsigned*)&g_arr[blockIdx.x] = ep;
      while (*(volatile unsigned*)&g_rel < ep) { }
    }
  }
  __syncthreads();
  __threadfence();
}

// tf32 warp tile 64x32 (mi4 x ni4), k-block 32 floats, smem row stride 36 u32
__device__ __forceinline__ void compute_64x32(const float* Af, const float* Bf,
      float acc[4][4][4], int wm, int wn, int g, int tg){
  const unsigned* As = (const unsigned*)Af;
  const unsigned* Bs = (const unsigned*)Bf;
#pragma unroll
  for (int ks = 0; ks < 32; ks += 8){
    unsigned a[4][4], b[4][2];
#pragma unroll
    for (int mi = 0; mi < 4; mi++){
      int r = wm + mi*16 + g;
      a[mi][0] = As[r*36 + ks+tg];
      a[mi][1] = As[(r+8)*36 + ks+tg];
      a[mi][2] = As[r*36 + ks+tg+4];
      a[mi][3] = As[(r+8)*36 + ks+tg+4];
    }
#pragma unroll
    for (int ni = 0; ni < 4; ni++){
      int rr = wn + ni*8 + g;
      b[ni][0] = Bs[rr*36 + ks+tg];
      b[ni][1] = Bs[rr*36 + ks+tg+4];
    }
#pragma unroll
    for (int mi = 0; mi < 4; mi++)
#pragma unroll
      for (int ni = 0; ni < 4; ni++)
        mma_tf32(acc[mi][ni], a[mi], b[ni]);
  }
}

// fp16 warp tile 64x16 (mi4 x ni2), k-block 64 halves, smem row stride 72 halves (36 u32)
__device__ __forceinline__ void compute_64x16h(const __half* Ah, const __half* Bh,
      float acc[4][2][4], int wm, int wn, int g, int tg){
  const unsigned* As = (const unsigned*)Ah;
  const unsigned* Bs = (const unsigned*)Bh;
#pragma unroll
  for (int ks = 0; ks < 64; ks += 16){
    int ko = ks/2 + tg;
    unsigned a[4][4], b[2][2];
#pragma unroll
    for (int mi = 0; mi < 4; mi++){
      int r = wm + mi*16 + g;
      a[mi][0] = As[r*36 + ko];
      a[mi][1] = As[(r+8)*36 + ko];
      a[mi][2] = As[r*36 + ko + 4];
      a[mi][3] = As[(r+8)*36 + ko + 4];
    }
#pragma unroll
    for (int ni = 0; ni < 2; ni++){
      int rr = wn + ni*8 + g;
      b[ni][0] = Bs[rr*36 + ko];
      b[ni][1] = Bs[rr*36 + ko + 4];
    }
#pragma unroll
    for (int mi = 0; mi < 4; mi++)
#pragma unroll
      for (int ni = 0; ni < 2; ni++)
        mma_fp16(acc[mi][ni], a[mi], b[ni]);
  }
}

// ---------------- prep: weights -> fp16 (recurrence) / tf32 (rest) ----------------
#define S_WC  3145728L
#define S_WH  3145728L
#define S_WE  2560000L
#define S_WX   524288L
#define S_WD  2588672L
__global__ void __launch_bounds__(256) prep_all(
    const float* __restrict__ w_hc, const float* __restrict__ edge_c,
    const float* __restrict__ w_hh, const float* __restrict__ edge_h,
    const float* __restrict__ embW, const float* __restrict__ wxcW,
    const float* __restrict__ wxhW, const float* __restrict__ decW)
{
  long i = (long)blockIdx.x*256 + threadIdx.x;
  const long F4 = (long)Hh*Hh/4;
  if (i < S_WC){
    float4 v = (i < F4) ? ((const float4*)w_hc)[i] : ((const float4*)edge_c)[i-F4];
    ((uint2*)g_Wc)[i] = pack4h(v);
    return;
  }
  if ((i -= S_WC) < S_WH){
    float4 v = (i < F4) ? ((const float4*)w_hh)[i] : ((const float4*)edge_h)[i-F4];
    ((uint2*)g_Wh)[i] = pack4h(v);
    return;
  }
  float4 v; float4* dst;
  if ((i -= S_WH) < S_WE){
    v = ((const float4*)embW)[i];
    dst = ((float4*)g_We) + i;
  } else if ((i -= S_WE) < S_WX){
    const long G4 = (long)Hh*Ee/4;
    v = (i < G4) ? ((const float4*)wxcW)[i] : ((const float4*)wxhW)[i-G4];
    dst = ((float4*)g_Wx) + i;
  } else if ((i -= S_WX) < S_WD){
    long row = (i*4) >> 10;
    v = (row < Vv) ? ((const float4*)decW)[i] : make_float4(0.f,0.f,0.f,0.f);
    dst = ((float4*)g_Wd) + i;
  } else return;
  float4 r; r.x=rndtf(v.x); r.y=rndtf(v.y); r.z=rndtf(v.z); r.w=rndtf(v.w);
  *dst = r;
}

// ---------------- phase 1: input projections (tf32) ----------------
__global__ void __launch_bounds__(256) xproj_kernel(
    const int* __restrict__ tokens,
    const float* __restrict__ wxcB, const float* __restrict__ wxhB)
{
  extern __shared__ unsigned char smraw[];
  float* Ash = (float*)smraw;               // PIPE * 128*36 floats
  float* Bsh = (float*)smraw + PIPE*4608;   // PIPE * 128*36 floats
  __shared__ int toks[128];
  const int tid = threadIdx.x;
  const int n0 = blockIdx.x * 128;
  const int m0 = blockIdx.y * 128;
  const int mat = blockIdx.z;
  const float* W    = g_Wx + (size_t)mat*Hh*Ee;
  const float* bias = mat ? wxhB : wxcB;
  float* Cout = mat ? g_XH : g_XC;
  if (tid < 128) toks[tid] = tokens[m0 + tid];
  __syncthreads();
  const int lane = tid & 31, warp = tid >> 5;
  const int wm = (warp & 1) * 64, wn = (warp >> 1) * 32;
  const int g = lane >> 2, tg = lane & 3;

  float acc[4][4][4];
#pragma unroll
  for (int a=0;a<4;a++)
#pragma unroll
    for (int b=0;b<4;b++)
#pragma unroll
      for (int c=0;c<4;c++) acc[a][b][c]=0.f;

  auto load_tile = [&](int p, int kbi){
    int kb = kbi * 32;
#pragma unroll
    for (int i = 0; i < 4; i++){
      int idx = tid + i*256, row = idx>>3, c4 = (idx&7)*4;
      cpa16(&Ash[p*4608 + row*36 + c4], g_We + (size_t)toks[row]*Ee + kb + c4);
      cpa16(&Bsh[p*4608 + row*36 + c4], W + (size_t)(n0+row)*Ee + kb + c4);
    }
  };

#pragma unroll
  for (int p = 0; p < PIPE-1; p++){ load_tile(p, p); cpa_commit(); }
  for (int it = 0; it < 32; it++){
    cpa_wait<PIPE-2>();
    __syncthreads();
    int nx = it + PIPE - 1;
    if (nx < 32) load_tile(nx % PIPE, nx);
    cpa_commit();
    compute_64x32(Ash + (it%PIPE)*4608, Bsh + (it%PIPE)*4608, acc, wm, wn, g, tg);
  }

#pragma unroll
  for (int mi=0; mi<4; mi++){
    int r = m0 + wm + mi*16 + g;
#pragma unroll
    for (int ni=0; ni<4; ni++){
      int c = n0 + wn + ni*8 + 2*tg;
      float b0 = bias[c], b1 = bias[c+1];
      size_t o = (size_t)r*Hh + c;
      Cout[o]        = acc[mi][ni][0] + b0;
      Cout[o+1]      = acc[mi][ni][1] + b1;
      Cout[o+8*Hh]   = acc[mi][ni][2] + b0;
      Cout[o+8*Hh+1] = acc[mi][ni][3] + b1;
    }
  }
}

// ---------------- phase 2: persistent recurrence (fp16 mma) ----------------
// 128 CTAs: kc(4) x nt(16) x mat(2). CTA tile 128(M) x 64(N) x 256(K).
__global__ void __launch_bounds__(256) rnn_kernel(float* __restrict__ outp)
{
  extern __shared__ unsigned char smraw[];
  __half* Aw = (__half*)smraw;              // 4 * 128*72 halves
  __half* Bw = (__half*)smraw + 4*9216;     // 4 * 64*72 halves
  __shared__ float red[9];
  const int tid = threadIdx.x;
  const int bid = blockIdx.x;
  const int lane = tid & 31, warp = tid >> 5;
  const int wm = (warp & 1) * 64, wn = (warp >> 1) * 16;
  const int g = lane >> 2, tg = lane & 3;
  const int kc  = bid & 3;
  const int nt  = (bid >> 2) & 15;
  const int mat = bid >> 6;
  const int n0 = nt * 64;
  const int k0 = kc * 256;
  const int f  = bid * 256 + tid;      // float4 index over 128x1024
  unsigned ep = 0;

  const __half* Wbase = mat ? g_Wh : g_Wc;

  auto load_B = [&](int s){
    const __half* W = Wbase + (size_t)s*Hh*Hh;
#pragma unroll
    for (int i = 0; i < 8; i++){
      int idx = tid + i*256;
      int kb = idx >> 9;
      int j  = idx & 511;
      int row = j >> 3, c8 = (j & 7) * 8;
      cpa16(&Bw[kb*4608 + row*72 + c8], W + (size_t)(n0+row)*Hh + k0 + kb*64 + c8);
    }
  };
  auto load_A = [&](int kb){
#pragma unroll
    for (int i = 0; i < 4; i++){
      int idx = tid + i*256, row = idx>>3, c8 = (idx&7)*8;
      cpa16(&Aw[kb*9216 + row*72 + c8], g_Hhp + (size_t)row*Hh + k0 + kb*64 + c8);
    }
  };

  // prefetch stage-0 weights immediately (independent of h)
  load_B(0); cpa_commit();

  // h0 = 0
  {
    ((float4*)g_H)[f] = make_float4(0.f,0.f,0.f,0.f);
    uint2 z2; z2.x = 0u; z2.y = 0u;
    ((uint2*)g_Hhp)[f] = z2;
  }
  gsync(ep);

  for (int t = 0; t < Tt; t++){
    for (int s = 0; s < NBLK; s++){
      float acc[4][2][4];
#pragma unroll
      for (int a=0;a<4;a++)
#pragma unroll
        for (int b2=0;b2<2;b2++)
#pragma unroll
          for (int c=0;c<4;c++) acc[a][b2][c]=0.f;

      load_A(0); cpa_commit();
      load_A(1); cpa_commit();
      load_A(2); cpa_commit();
      load_A(3); cpa_commit();

      cpa_wait<3>(); __syncthreads();
      compute_64x16h(Aw + 0*9216, Bw + 0*4608, acc, wm, wn, g, tg);
      cpa_wait<2>(); __syncthreads();
      compute_64x16h(Aw + 1*9216, Bw + 1*4608, acc, wm, wn, g, tg);
      cpa_wait<1>(); __syncthreads();
      compute_64x16h(Aw + 2*9216, Bw + 2*4608, acc, wm, wn, g, tg);
      cpa_wait<0>(); __syncthreads();
      compute_64x16h(Aw + 3*9216, Bw + 3*4608, acc, wm, wn, g, tg);

      // all warps done reading Bw -> prefetch next stage's weights
      __syncthreads();
      {
        int sn = s + 1; if (sn == NBLK) sn = 0;
        load_B(sn); cpa_commit();
      }

      // write split-K partial (f32)
      float* Pd = (mat ? g_Ph : g_Pc) + ((size_t)kc << 17);
#pragma unroll
      for (int mi=0; mi<4; mi++){
        int r = wm + mi*16 + g;
#pragma unroll
        for (int ni=0; ni<2; ni++){
          int c = n0 + wn + ni*8 + 2*tg;
          Pd[(size_t)r*Hh + c]       = acc[mi][ni][0];
          Pd[(size_t)r*Hh + c+1]     = acc[mi][ni][1];
          Pd[(size_t)(r+8)*Hh + c]   = acc[mi][ni][2];
          Pd[(size_t)(r+8)*Hh + c+1] = acc[mi][ni][3];
        }
      }
      gsync(ep);

      // fused reduce + gate + activation + blend; thread f owns 4 floats of row bid
      {
        float4 sc = make_float4(0.f,0.f,0.f,0.f);
        float4 sh = make_float4(0.f,0.f,0.f,0.f);
#pragma unroll
        for (int k = 0; k < 4; k++){
          float4 a  = ((const float4*)(g_Pc + ((size_t)k<<17)))[f];
          sc.x += a.x; sc.y += a.y; sc.z += a.z; sc.w += a.w;
          float4 b2 = ((const float4*)(g_Ph + ((size_t)k<<17)))[f];
          sh.x += b2.x; sh.y += b2.y; sh.z += b2.z; sh.w += b2.w;
        }
        if (s == 0){
          float4 a  = ((const float4*)g_XC)[((size_t)t<<15) + f];
          sc.x += a.x; sc.y += a.y; sc.z += a.z; sc.w += a.w;
          float4 b2 = ((const float4*)g_XH)[((size_t)t<<15) + f];
          sh.x += b2.x; sh.y += b2.y; sh.z += b2.z; sh.w += b2.w;
        }
        float4 h = ((const float4*)g_H)[f];
        const bool use_tanh = (s == 0) || (s & 1);
        float gx = sigm(sc.x), gy = sigm(sc.y), gz = sigm(sc.z), gw = sigm(sc.w);
        float ax = use_tanh ? tanhf(sh.x) : fmaxf(sh.x, 0.f);
        float ay = use_tanh ? tanhf(sh.y) : fmaxf(sh.y, 0.f);
        float az = use_tanh ? tanhf(sh.z) : fmaxf(sh.z, 0.f);
        float aw = use_tanh ? tanhf(sh.w) : fmaxf(sh.w, 0.f);
        float4 hn;
        hn.x = gx*ax + (1.f-gx)*h.x;
        hn.y = gy*ay + (1.f-gy)*h.y;
        hn.z = gz*az + (1.f-gz)*h.z;
        hn.w = gw*aw + (1.f-gw)*h.w;

        if (s == NBLK-1){
          // pre-clip output for decoder: tf32-rounded f32
          float4 pre;
          pre.x=rndtf(hn.x); pre.y=rndtf(hn.y); pre.z=rndtf(hn.z); pre.w=rndtf(hn.w);
          ((float4*)g_OUT)[((size_t)t<<15) + f] = pre;
          // fused per-row norm clip: this CTA owns exactly row bid
          float ss = hn.x*hn.x + hn.y*hn.y + hn.z*hn.z + hn.w*hn.w;
#pragma unroll
          for (int off = 16; off > 0; off >>= 1) ss += __shfl_xor_sync(0xffffffffu, ss, off);
          if (lane == 0) red[warp] = ss;
          __syncthreads();
          if (tid == 0){
            float tot = 0.f;
#pragma unroll
            for (int w2 = 0; w2 < 8; w2++) tot += red[w2];
            float nrm = sqrtf(tot);
            red[8] = (nrm > 25.f) ? (25.f / nrm) : 1.f;
          }
          __syncthreads();
          float scl = red[8];
          hn.x *= scl; hn.y *= scl; hn.z *= scl; hn.w *= scl;
        }
        ((float4*)g_H)[f] = hn;
        ((uint2*)g_Hhp)[f] = pack4h(hn);
      }
      gsync(ep);
    }
  }

  // hT (clipped final hidden) appended after decoded
  {
    float4 h = ((const float4*)g_H)[f];
    float* o = outp + (size_t)Tt*Bb*Vv + (size_t)f*4;
    o[0]=h.x; o[1]=h.y; o[2]=h.z; o[3]=h.w;
  }
}

// ---------------- phase 3: decoder GEMM (tf32) ----------------
__global__ void __launch_bounds__(256) dec_kernel(
  const float* __restrict__ decB, float* __restrict__ outp)
{
  extern __shared__ unsigned char smraw[];
  float* Ash = (float*)smraw;
  float* Bsh = (float*)smraw + PIPE*4608;
  const int tid = threadIdx.x;
  const int n0 = blockIdx.x * 128;
  const int m0 = blockIdx.y * 128;
  const int lane = tid & 31, warp = tid >> 5;
  const int wm = (warp & 1) * 64, wn = (warp >> 1) * 32;
  const int g = lane >> 2, tg = lane & 3;
  float acc[4][4][4];
#pragma unroll
  for (int a=0;a<4;a++)
#pragma unroll
    for (int b=0;b<4;b++)
#pragma unroll
      for (int c=0;c<4;c++) acc[a][b][c]=0.f;

  auto load_tile = [&](int p, int kbi){
    int kb = kbi * 32;
#pragma unroll
    for (int i = 0; i < 4; i++){
      int idx = tid + i*256, row = idx>>3, c4 = (idx&7)*4;
      cpa16(&Ash[p*4608 + row*36 + c4], g_OUT + (size_t)(m0+row)*Hh + kb + c4);
      cpa16(&Bsh[p*4608 + row*36 + c4], g_Wd + (size_t)(n0+row)*Hh + kb + c4);
    }
  };

#pragma unroll
  for (int p = 0; p < PIPE-1; p++){ load_tile(p, p); cpa_commit(); }
  for (int it = 0; it < 32; it++){
    cpa_wait<PIPE-2>();
    __syncthreads();
    int nx = it + PIPE - 1;
    if (nx < 32) load_tile(nx % PIPE, nx);
    cpa_commit();
    compute_64x32(Ash + (it%PIPE)*4608, Bsh + (it%PIPE)*4608, acc, wm, wn, g, tg);
  }

#pragma unroll
  for (int mi=0;mi<4;mi++){
    int r = m0 + wm + mi*16 + g;
#pragma unroll
    for (int ni=0;ni<4;ni++){
      int c = n0 + wn + ni*8 + 2*tg;
      if (c < Vv){
        float b0 = decB[c], b1 = decB[c+1];
        size_t o  = (size_t)r*Vv + c;
        size_t o2 = o + (size_t)8*Vv;
        outp[o]    = acc[mi][ni][0] + b0;
        outp[o+1]  = acc[mi][ni][1] + b1;
        outp[o2]   = acc[mi][ni][2] + b0;
        outp[o2+1] = acc[mi][ni][3] + b1;
      }
    }
  }
}

// ---------------- launch ----------------
extern "C" void kernel_launch(void* const* d_in, const int* in_sizes, int n_in,
                              void* d_out, int out_size){
  const int*   tokens = (const int*)  d_in[0];
  const float* embW   = (const float*)d_in[1];
  const float* wxcW   = (const float*)d_in[2];
  const float* wxcB   = (const float*)d_in[3];
  const float* wxhW   = (const float*)d_in[4];
  const float* wxhB   = (const float*)d_in[5];
  const float* w_hc   = (const float*)d_in[6];
  const float* w_hh   = (const float*)d_in[7];
  const float* edge_h = (const float*)d_in[8];
  const float* edge_c = (const float*)d_in[9];
  const float* decW   = (const float*)d_in[10];
  const float* decB   = (const float*)d_in[11];
  float* outp = (float*)d_out;
  (void)in_sizes; (void)n_in; (void)out_size;

  const int RNN_SMEM  = (4*9216 + 4*4608) * 2;   // 110592 B (halves)
  const int GEMM_SMEM = PIPE * 2 * 4608 * 4;     // 110592 B (floats)
  cudaFuncSetAttribute(xproj_kernel, cudaFuncAttributeMaxDynamicSharedMemorySize, GEMM_SMEM);
  cudaFuncSetAttribute(rnn_kernel,   cudaFuncAttributeMaxDynamicSharedMemorySize, RNN_SMEM);
  cudaFuncSetAttribute(dec_kernel,   cudaFuncAttributeMaxDynamicSharedMemorySize, GEMM_SMEM);

  // reset barrier flags
  void *pArr = nullptr, *pRel = nullptr;
  cudaGetSymbolAddress(&pArr, g_arr);
  cudaGetSymbolAddress(&pRel, g_rel);
  cudaMemsetAsync(pArr, 0, sizeof(unsigned)*GRID_R);
  cudaMemsetAsync(pRel, 0, sizeof(unsigned));

  const long PREP_TOTAL = S_WC + S_WH + S_WE + S_WX + S_WD;
  prep_all<<<(unsigned)((PREP_TOTAL + 255) / 256), 256>>>(
      w_hc, edge_c, w_hh, edge_h, embW, wxcW, wxhW, decW);

  xproj_kernel<<<dim3(8, 64, 2), 256, GEMM_SMEM>>>(tokens, wxcB, wxhB);
  rnn_kernel<<<GRID_R, 256, RNN_SMEM>>>(outp);
  dec_kernel<<<dim3(VPAD/128, 64), 256, GEMM_SMEM>>>(decB, outp);
}